// round 5
// baseline (speedup 1.0000x reference)
#include <cuda_runtime.h>
#include <math.h>
#include <stdint.h>

#define EMB   768
#define DFF   3072
#define NTOK  16384
#define HEADS 12
#define HD    64
#define SEQ   1024
#define BATCH 16
#define QKV3  2304

// ---------------- scratch (no allocations allowed) ----------------
__device__ float g_h   [NTOK * EMB];
__device__ float g_qkv [NTOK * QKV3];
__device__ float g_ctx [NTOK * EMB];
__device__ float g_x1  [NTOK * EMB];
__device__ float g_h2  [NTOK * EMB];
__device__ float g_ff  [NTOK * DFF];
// pre-transposed + tf32-rounded weights
__device__ float g_wqkvT[QKV3 * EMB];
__device__ float g_woT  [EMB * EMB];
__device__ float g_w1T  [DFF * EMB];
__device__ float g_w2T  [EMB * DFF];
__device__ float g_bqkv [QKV3];

// ---------------- helpers ----------------
__device__ __forceinline__ float f2tf(float f) {
    unsigned u;
    asm("cvt.rna.tf32.f32 %0, %1;" : "=r"(u) : "f"(f));
    return __uint_as_float(u);
}

__device__ __forceinline__ void mma8(float* c, const unsigned* a, const unsigned* b) {
    asm volatile(
        "mma.sync.aligned.m16n8k8.row.col.f32.tf32.tf32.f32 "
        "{%0,%1,%2,%3}, {%4,%5,%6,%7}, {%8,%9}, {%0,%1,%2,%3};"
        : "+f"(c[0]), "+f"(c[1]), "+f"(c[2]), "+f"(c[3])
        : "r"(a[0]), "r"(a[1]), "r"(a[2]), "r"(a[3]), "r"(b[0]), "r"(b[1]));
}

__device__ __forceinline__ void ldsm4(unsigned& r0, unsigned& r1, unsigned& r2,
                                      unsigned& r3, uint32_t addr) {
    asm volatile("ldmatrix.sync.aligned.m8n8.x4.shared.b16 {%0,%1,%2,%3}, [%4];"
                 : "=r"(r0), "=r"(r1), "=r"(r2), "=r"(r3) : "r"(addr));
}

#define CP_ASYNC16(dst, src) \
    asm volatile("cp.async.cg.shared.global [%0], [%1], 16;" :: "r"(dst), "l"(src))
#define CP_COMMIT() asm volatile("cp.async.commit_group;")
#define CP_WAIT2()  asm volatile("cp.async.wait_group 2;")
#define CP_WAIT1()  asm volatile("cp.async.wait_group 1;")
#define CP_WAIT0()  asm volatile("cp.async.wait_group 0;")

__device__ __forceinline__ float block_reduce_sum(float v, float* red) {
    #pragma unroll
    for (int off = 16; off > 0; off >>= 1)
        v += __shfl_xor_sync(0xffffffffu, v, off);
    int w = threadIdx.x >> 5;
    if ((threadIdx.x & 31) == 0) red[w] = v;
    __syncthreads();
    if (threadIdx.x < 32) {
        float t = (threadIdx.x < 8) ? red[threadIdx.x] : 0.0f;
        #pragma unroll
        for (int off = 4; off > 0; off >>= 1)
            t += __shfl_xor_sync(0xffffffffu, t, off);
        if (threadIdx.x == 0) red[0] = t;
    }
    __syncthreads();
    float r = red[0];
    __syncthreads();
    return r;
}

// ---------------- prep: all 6 weight transposes in ONE launch ----------------
// grid (96, 96, 6); blocks beyond a weight's extent early-out.
__global__ void __launch_bounds__(256) transpose_all(
    const float* __restrict__ Wq, const float* __restrict__ Wk,
    const float* __restrict__ Wv, const float* __restrict__ Wo,
    const float* __restrict__ W1, const float* __restrict__ W2)
{
    const float* src; float* dst; int K, N;
    switch (blockIdx.z) {
        case 0: src = Wq; dst = g_wqkvT;               K = EMB; N = EMB; break;
        case 1: src = Wk; dst = g_wqkvT + EMB * EMB;   K = EMB; N = EMB; break;
        case 2: src = Wv; dst = g_wqkvT + 2*EMB*EMB;   K = EMB; N = EMB; break;
        case 3: src = Wo; dst = g_woT;                 K = EMB; N = EMB; break;
        case 4: src = W1; dst = g_w1T;                 K = EMB; N = DFF; break;
        default:src = W2; dst = g_w2T;                 K = DFF; N = EMB; break;
    }
    const int n0 = blockIdx.x * 32;
    const int k0 = blockIdx.y * 32;
    if (n0 >= N || k0 >= K) return;

    __shared__ float t[32][33];
    const int tx = threadIdx.x & 31;
    const int ty = threadIdx.x >> 5;
    #pragma unroll
    for (int j = 0; j < 4; j++)
        t[ty + j * 8][tx] = src[(size_t)(k0 + ty + j * 8) * N + n0 + tx];
    __syncthreads();
    #pragma unroll
    for (int j = 0; j < 4; j++)
        dst[(size_t)(n0 + ty + j * 8) * K + k0 + tx] = f2tf(t[tx][ty + j * 8]);
}

__global__ void bias_concat(const float* bq, const float* bk, const float* bv,
                            float* out)
{
    int i = blockIdx.x * 256 + threadIdx.x;
    if (i < QKV3) {
        float v = (i < EMB) ? bq[i] : (i < 2 * EMB) ? bk[i - EMB] : bv[i - 2 * EMB];
        out[i] = v;
    }
}

// ---------------- LayerNorm (outputs tf32-rounded) ----------------
__global__ void __launch_bounds__(256) ln_kernel(
    const float* __restrict__ x, const float* __restrict__ gw,
    const float* __restrict__ bw, float* __restrict__ out)
{
    __shared__ float red[32];
    const int row = blockIdx.x;
    const float* xr = x + (size_t)row * EMB;

    float vals[3];
    float lsum = 0.0f;
    #pragma unroll
    for (int i = 0; i < 3; i++) {
        vals[i] = xr[threadIdx.x + i * 256];
        lsum += vals[i];
    }
    float mu = block_reduce_sum(lsum, red) * (1.0f / EMB);

    float ls2 = 0.0f;
    #pragma unroll
    for (int i = 0; i < 3; i++) {
        float d = vals[i] - mu;
        ls2 += d * d;
    }
    float var = block_reduce_sum(ls2, red) * (1.0f / EMB);
    float rs = rsqrtf(var + 1e-5f);

    float* outr = out + (size_t)row * EMB;
    #pragma unroll
    for (int i = 0; i < 3; i++) {
        int c = threadIdx.x + i * 256;
        outr[c] = f2tf((vals[i] - mu) * rs * gw[c] + bw[c]);
    }
}

// ---------------- fused flash attention (tf32 tensor cores) ----------------
#define QP 68
#define VP 72
#define PP 132

__global__ void __launch_bounds__(256) flash_kernel(
    const float* __restrict__ qkv, float* __restrict__ ctx)
{
    extern __shared__ float fs[];
    const uint32_t base  = (uint32_t)__cvta_generic_to_shared(fs);
    const uint32_t kBase = base;
    const uint32_t vBase = kBase + 2u * 128 * QP * 4;
    float* Pfs = fs + 2 * 128 * QP + 2 * 128 * VP;

    const int tid  = threadIdx.x;
    const int w    = tid >> 5;
    const int lane = tid & 31;
    const int gi   = lane >> 2;
    const int li   = lane & 3;
    const int q0   = blockIdx.x * 128;
    const int z    = blockIdx.y;
    const int b    = z / HEADS, h = z % HEADS;

    const float* qptr = qkv + (size_t)(b * SEQ + q0) * QKV3 + h * HD;
    const float* kptr = qkv + (size_t)(b * SEQ) * QKV3 + EMB + h * HD;
    const float* vptr = qkv + (size_t)(b * SEQ) * QKV3 + 2 * EMB + h * HD;

    // ---- load Q tile into V-stage-1 region (reused later) ----
    {
        uint32_t dst = vBase + 128u * VP * 4;
        #pragma unroll
        for (int i = 0; i < 8; i++) {
            int idx = tid + i * 256;
            int r = idx >> 4, c = (idx & 15) * 4;
            CP_ASYNC16(dst + (uint32_t)(r * QP + c) * 4, qptr + (size_t)r * QKV3 + c);
        }
    }
    CP_COMMIT();
    CP_WAIT0();
    __syncthreads();

    unsigned qf[8][4];
    {
        uint32_t qb = vBase + 128u * VP * 4;
        int rowA = w * 16 + (lane & 15);
        int kqA  = (lane >> 4) * 4;
        #pragma unroll
        for (int ks = 0; ks < 8; ks++)
            ldsm4(qf[ks][0], qf[ks][1], qf[ks][2], qf[ks][3],
                  qb + (uint32_t)(rowA * QP + ks * 8 + kqA) * 4);
    }
    __syncthreads();

    float m0 = -1e30f, m1 = -1e30f, l0 = 0.0f, l1 = 0.0f;
    float O[8][4];
    #pragma unroll
    for (int nt = 0; nt < 8; nt++)
        #pragma unroll
        for (int t = 0; t < 4; t++) O[nt][t] = 0.0f;

    const int rowB = ((lane >> 4) & 1) * 8 + (lane & 7);
    const int kqB  = ((lane >> 3) & 1) * 4;
    const int prow0 = w * 16 + gi;
    const int prow1 = prow0 + 8;

    {
        const float* kp = kptr;
        const float* vp = vptr;
        #pragma unroll
        for (int i = 0; i < 8; i++) {
            int idx = tid + i * 256;
            int r = idx >> 4, c = (idx & 15) * 4;
            CP_ASYNC16(kBase + (uint32_t)(r * QP + c) * 4, kp + (size_t)r * QKV3 + c);
            CP_ASYNC16(vBase + (uint32_t)(r * VP + c) * 4, vp + (size_t)r * QKV3 + c);
        }
        CP_COMMIT();
    }

    for (int t = 0; t < 8; t++) {
        const int st = t & 1;
        if (t < 7) {
            const int ns = st ^ 1;
            const float* kp = kptr + (size_t)(t + 1) * 128 * QKV3;
            const float* vp = vptr + (size_t)(t + 1) * 128 * QKV3;
            uint32_t kd = kBase + (uint32_t)ns * 128 * QP * 4;
            uint32_t vd = vBase + (uint32_t)ns * 128 * VP * 4;
            #pragma unroll
            for (int i = 0; i < 8; i++) {
                int idx = tid + i * 256;
                int r = idx >> 4, c = (idx & 15) * 4;
                CP_ASYNC16(kd + (uint32_t)(r * QP + c) * 4, kp + (size_t)r * QKV3 + c);
                CP_ASYNC16(vd + (uint32_t)(r * VP + c) * 4, vp + (size_t)r * QKV3 + c);
            }
            CP_COMMIT();
            CP_WAIT1();
        } else {
            CP_WAIT0();
        }
        __syncthreads();

        float acc[16][4];
        #pragma unroll
        for (int nt = 0; nt < 16; nt++)
            #pragma unroll
            for (int c = 0; c < 4; c++) acc[nt][c] = 0.0f;

        uint32_t kb = kBase + (uint32_t)st * 128 * QP * 4;
        #pragma unroll
        for (int ks = 0; ks < 8; ks++) {
            unsigned bf[16][2];
            #pragma unroll
            for (int p = 0; p < 8; p++) {
                unsigned r0, r1, r2, r3;
                ldsm4(r0, r1, r2, r3,
                      kb + (uint32_t)((rowB + p * 16) * QP + ks * 8 + kqB) * 4);
                bf[2 * p][0] = r0; bf[2 * p][1] = r1;
                bf[2 * p + 1][0] = r2; bf[2 * p + 1][1] = r3;
            }
            #pragma unroll
            for (int nt = 0; nt < 16; nt++)
                mma8(acc[nt], qf[ks], bf[nt]);
        }

        float mx0 = -1e30f, mx1 = -1e30f;
        #pragma unroll
        for (int nt = 0; nt < 16; nt++) {
            acc[nt][0] *= 0.125f; acc[nt][1] *= 0.125f;
            acc[nt][2] *= 0.125f; acc[nt][3] *= 0.125f;
            mx0 = fmaxf(mx0, fmaxf(acc[nt][0], acc[nt][1]));
            mx1 = fmaxf(mx1, fmaxf(acc[nt][2], acc[nt][3]));
        }
        mx0 = fmaxf(mx0, __shfl_xor_sync(0xffffffffu, mx0, 1));
        mx0 = fmaxf(mx0, __shfl_xor_sync(0xffffffffu, mx0, 2));
        mx1 = fmaxf(mx1, __shfl_xor_sync(0xffffffffu, mx1, 1));
        mx1 = fmaxf(mx1, __shfl_xor_sync(0xffffffffu, mx1, 2));
        float mn0 = fmaxf(m0, mx0), mn1 = fmaxf(m1, mx1);
        float a0 = __expf(m0 - mn0), a1 = __expf(m1 - mn1);
        m0 = mn0; m1 = mn1;

        float s0 = 0.0f, s1 = 0.0f;
        #pragma unroll
        for (int nt = 0; nt < 16; nt++) {
            float p0 = __expf(acc[nt][0] - mn0);
            float p1 = __expf(acc[nt][1] - mn0);
            float p2 = __expf(acc[nt][2] - mn1);
            float p3 = __expf(acc[nt][3] - mn1);
            s0 += p0 + p1; s1 += p2 + p3;
            int col = nt * 8 + 2 * li;
            *(float2*)&Pfs[prow0 * PP + col] = make_float2(f2tf(p0), f2tf(p1));
            *(float2*)&Pfs[prow1 * PP + col] = make_float2(f2tf(p2), f2tf(p3));
        }
        s0 += __shfl_xor_sync(0xffffffffu, s0, 1);
        s0 += __shfl_xor_sync(0xffffffffu, s0, 2);
        s1 += __shfl_xor_sync(0xffffffffu, s1, 1);
        s1 += __shfl_xor_sync(0xffffffffu, s1, 2);
        l0 = l0 * a0 + s0;
        l1 = l1 * a1 + s1;

        #pragma unroll
        for (int nt = 0; nt < 8; nt++) {
            O[nt][0] *= a0; O[nt][1] *= a0;
            O[nt][2] *= a1; O[nt][3] *= a1;
        }
        __syncwarp();

        uint32_t vb = vBase + (uint32_t)st * 128 * VP * 4;
        const unsigned* Pu = (const unsigned*)Pfs;
        #pragma unroll
        for (int kk = 0; kk < 16; kk++) {
            const int k0 = kk * 8;
            unsigned af[4];
            af[0] = Pu[prow0 * PP + k0 + li];
            af[1] = Pu[prow1 * PP + k0 + li];
            af[2] = Pu[prow0 * PP + k0 + li + 4];
            af[3] = Pu[prow1 * PP + k0 + li + 4];
            const unsigned* Vu = (const unsigned*)fs;
            uint32_t vw = (vb - base) >> 2;
            #pragma unroll
            for (int nt = 0; nt < 8; nt++) {
                unsigned bfr[2];
                bfr[0] = Vu[vw + (k0 + li) * VP + nt * 8 + gi];
                bfr[1] = Vu[vw + (k0 + li + 4) * VP + nt * 8 + gi];
                mma8(O[nt], af, bfr);
            }
        }
        __syncthreads();
    }

    float inv0 = 1.0f / l0, inv1 = 1.0f / l1;
    float* out0 = ctx + (size_t)(b * SEQ + q0 + w * 16 + gi) * EMB + h * HD;
    float* out1 = out0 + (size_t)8 * EMB;
    #pragma unroll
    for (int nt = 0; nt < 8; nt++) {
        int col = nt * 8 + 2 * li;
        *(float2*)(out0 + col) = make_float2(f2tf(O[nt][0] * inv0), f2tf(O[nt][1] * inv0));
        *(float2*)(out1 + col) = make_float2(f2tf(O[nt][2] * inv1), f2tf(O[nt][3] * inv1));
    }
}

// ---------------- tf32 GEMM, 3-stage cp.async pipeline, ldmatrix ----------------
template<int BM, int BN, int WM, int WN, bool DO_GELU, bool DO_RESID, bool RNA_OUT>
__global__ void __launch_bounds__(256) mma_gemm(
    const float* __restrict__ A, const float* __restrict__ B,
    const float* __restrict__ bias, const float* __restrict__ R,
    float* __restrict__ C, int M, int N, int K,
    int lda, int ldb, int ldc, float scale)
{
    constexpr int BK = 32, BKP = 36;
    constexpr int MT = WM / 16;
    constexpr int NT = WN / 8;
    constexpr int WARPS_N = BN / WN;
    constexpr int STAGE = (BM + BN) * BKP;

    extern __shared__ unsigned smem[];
    const uint32_t base = (uint32_t)__cvta_generic_to_shared(smem);

    const int tid  = threadIdx.x;
    const int w    = tid >> 5;
    const int lane = tid & 31;
    const int gi   = lane >> 2;
    const int li   = lane & 3;
    const int wn   = w % WARPS_N;
    const int wm   = w / WARPS_N;
    const int bm   = blockIdx.y * BM;
    const int bn   = blockIdx.x * BN;

    const int rowA = wm * WM + (lane & 15);
    const int kqA  = (lane >> 4) * 4;
    const int rowB = wn * WN + ((lane >> 4) & 1) * 8 + (lane & 7);
    const int kqB  = ((lane >> 3) & 1) * 4;

    auto load_tile = [&](int k0, int st) {
        uint32_t sA = base + (uint32_t)st * STAGE * 4;
        uint32_t sB = sA + BM * BKP * 4;
        #pragma unroll
        for (int i = 0; i < BM / 32; i++) {
            int idx = tid + i * 256;
            int r = idx >> 3, c = (idx & 7) * 4;
            CP_ASYNC16(sA + (uint32_t)(r * BKP + c) * 4,
                       A + (size_t)(bm + r) * lda + k0 + c);
        }
        #pragma unroll
        for (int i = 0; i < BN / 32; i++) {
            int idx = tid + i * 256;
            int r = idx >> 3, c = (idx & 7) * 4;
            CP_ASYNC16(sB + (uint32_t)(r * BKP + c) * 4,
                       B + (size_t)(bn + r) * ldb + k0 + c);
        }
    };

    float acc[MT][NT][4];
    #pragma unroll
    for (int i = 0; i < MT; i++)
        #pragma unroll
        for (int j = 0; j < NT; j++)
            #pragma unroll
            for (int t = 0; t < 4; t++) acc[i][j][t] = 0.0f;

    const int iters = K / BK;
    load_tile(0, 0);
    CP_COMMIT();
    load_tile(BK, 1);
    CP_COMMIT();

    int st = 0;
    for (int it = 0; it < iters; ++it) {
        if (it + 2 < iters) load_tile((it + 2) * BK, (it + 2) % 3);
        CP_COMMIT();
        CP_WAIT2();
        __syncthreads();

        uint32_t sA = base + (uint32_t)st * STAGE * 4;
        uint32_t sB = sA + BM * BKP * 4;

        #pragma unroll
        for (int ks = 0; ks < BK / 8; ks++) {
            const int kb = ks * 8;
            unsigned af[MT][4];
            #pragma unroll
            for (int mt = 0; mt < MT; mt++) {
                uint32_t ad = sA + (uint32_t)((rowA + mt * 16) * BKP + kb + kqA) * 4;
                ldsm4(af[mt][0], af[mt][1], af[mt][2], af[mt][3], ad);
            }
            unsigned bf[NT][2];
            #pragma unroll
            for (int p = 0; p < NT / 2; p++) {
                uint32_t ad = sB + (uint32_t)((rowB + p * 16) * BKP + kb + kqB) * 4;
                unsigned r0, r1, r2, r3;
                ldsm4(r0, r1, r2, r3, ad);
                bf[2 * p][0] = r0; bf[2 * p][1] = r1;
                bf[2 * p + 1][0] = r2; bf[2 * p + 1][1] = r3;
            }
            #pragma unroll
            for (int mt = 0; mt < MT; mt++)
                #pragma unroll
                for (int nt = 0; nt < NT; nt++)
                    mma8(acc[mt][nt], af[mt], bf[nt]);
        }
        __syncthreads();
        st = (st + 1 == 3) ? 0 : st + 1;
    }

    #pragma unroll
    for (int mt = 0; mt < MT; mt++) {
        #pragma unroll
        for (int nt = 0; nt < NT; nt++) {
            int row = bm + wm * WM + mt * 16 + gi;
            int col = bn + wn * WN + nt * 8 + 2 * li;
            float bi0 = 0.0f, bi1 = 0.0f;
            if (bias) { bi0 = bias[col]; bi1 = bias[col + 1]; }
            #pragma unroll
            for (int half = 0; half < 2; half++) {
                int rr = row + half * 8;
                float v0 = acc[mt][nt][half * 2 + 0] * scale + bi0;
                float v1 = acc[mt][nt][half * 2 + 1] * scale + bi1;
                if (DO_GELU) {
                    v0 = 0.5f * v0 * (1.0f + erff(v0 * 0.70710678118654752f));
                    v1 = 0.5f * v1 * (1.0f + erff(v1 * 0.70710678118654752f));
                }
                if (DO_RESID) {
                    float2 r2 = *(const float2*)(R + (size_t)rr * ldc + col);
                    v0 += r2.x; v1 += r2.y;
                }
                if (RNA_OUT) { v0 = f2tf(v0); v1 = f2tf(v1); }
                *(float2*)(C + (size_t)rr * ldc + col) = make_float2(v0, v1);
            }
        }
    }
}

// ---------------- launch ----------------
extern "C" void kernel_launch(void* const* d_in, const int* in_sizes, int n_in,
                              void* d_out, int out_size)
{
    const float* x     = (const float*)d_in[0];
    const float* ln1_g = (const float*)d_in[1];
    const float* ln1_b = (const float*)d_in[2];
    const float* Wq    = (const float*)d_in[3];
    const float* bq    = (const float*)d_in[4];
    const float* Wk    = (const float*)d_in[5];
    const float* bk    = (const float*)d_in[6];
    const float* Wv    = (const float*)d_in[7];
    const float* bv    = (const float*)d_in[8];
    const float* Wo    = (const float*)d_in[9];
    const float* bo    = (const float*)d_in[10];
    const float* ln2_g = (const float*)d_in[11];
    const float* ln2_b = (const float*)d_in[12];
    const float* W1    = (const float*)d_in[13];
    const float* b1    = (const float*)d_in[14];
    const float* W2    = (const float*)d_in[15];
    const float* b2    = (const float*)d_in[16];
    float* out = (float*)d_out;

    float *h, *qkv, *ctx, *x1, *h2, *ff;
    float *wqkvT, *woT, *w1T, *w2T, *bqkv;
    cudaGetSymbolAddress((void**)&h,     g_h);
    cudaGetSymbolAddress((void**)&qkv,   g_qkv);
    cudaGetSymbolAddress((void**)&ctx,   g_ctx);
    cudaGetSymbolAddress((void**)&x1,    g_x1);
    cudaGetSymbolAddress((void**)&h2,    g_h2);
    cudaGetSymbolAddress((void**)&ff,    g_ff);
    cudaGetSymbolAddress((void**)&wqkvT, g_wqkvT);
    cudaGetSymbolAddress((void**)&woT,   g_woT);
    cudaGetSymbolAddress((void**)&w1T,   g_w1T);
    cudaGetSymbolAddress((void**)&w2T,   g_w2T);
    cudaGetSymbolAddress((void**)&bqkv,  g_bqkv);

    const int SM_3S    = 3 * (128 + 128) * 36 * 4;                        // 110592
    const int SM_FLASH = (2 * 128 * QP + 2 * 128 * VP + 8 * 16 * PP) * 4; // 210944

    cudaFuncSetAttribute((const void*)mma_gemm<128,128,64,32,false,false,true>,
                         cudaFuncAttributeMaxDynamicSharedMemorySize, SM_3S);
    cudaFuncSetAttribute((const void*)mma_gemm<128,128,64,32,false,true,false>,
                         cudaFuncAttributeMaxDynamicSharedMemorySize, SM_3S);
    cudaFuncSetAttribute((const void*)mma_gemm<128,128,64,32,true,false,true>,
                         cudaFuncAttributeMaxDynamicSharedMemorySize, SM_3S);
    cudaFuncSetAttribute((const void*)flash_kernel,
                         cudaFuncAttributeMaxDynamicSharedMemorySize, SM_FLASH);

    // launch order matters for ncu (-s 5 captures launch index 5 = Wo GEMM)
    // 0. bias concat
    bias_concat<<<9, 256>>>(bq, bk, bv, bqkv);
    // 1. all weight transposes (single launch)
    transpose_all<<<dim3(96, 96, 6), 256>>>(Wq, Wk, Wv, Wo, W1, W2);
    // 2. LN1
    ln_kernel<<<NTOK, 256>>>(x, ln1_g, ln1_b, h);
    // 3. fused QKV (outputs tf32-rounded)
    mma_gemm<128,128,64,32,false,false,true><<<dim3(QKV3/128, NTOK/128), 256, SM_3S>>>(
        h, wqkvT, bqkv, nullptr, qkv, NTOK, QKV3, EMB, EMB, EMB, QKV3, 1.0f);
    // 4. fused flash attention -> ctx (tf32-rounded)
    flash_kernel<<<dim3(SEQ/128, BATCH*HEADS), 256, SM_FLASH>>>(qkv, ctx);
    // 5. x1 = ctx @ Wo + bo + x          <-- ncu capture target
    mma_gemm<128,128,64,32,false,true,false><<<dim3(EMB/128, NTOK/128), 256, SM_3S>>>(
        ctx, woT, bo, x, x1, NTOK, EMB, EMB, EMB, EMB, EMB, 1.0f);
    // 6. LN2
    ln_kernel<<<NTOK, 256>>>(x1, ln2_g, ln2_b, h2);
    // 7. ff = rna(gelu(h2 @ W1 + b1))
    mma_gemm<128,128,64,32,true,false,true><<<dim3(DFF/128, NTOK/128), 256, SM_3S>>>(
        h2, w1T, b1, nullptr, ff, NTOK, DFF, EMB, EMB, EMB, DFF, 1.0f);
    // 8. out = ff @ W2 + b2 + x1
    mma_gemm<128,128,64,32,false,true,false><<<dim3(EMB/128, NTOK/128), 256, SM_3S>>>(
        ff, w2T, b2, x1, out, NTOK, EMB, DFF, DFF, DFF, EMB, 1.0f);
}

// round 9
// speedup vs baseline: 1.0359x; 1.0359x over previous
#include <cuda_runtime.h>
#include <math.h>
#include <stdint.h>

#define EMB   768
#define DFF   3072
#define NTOK  16384
#define HEADS 12
#define HD    64
#define SEQ   1024
#define BATCH 16
#define QKV3  2304

// ---------------- scratch (no allocations allowed) ----------------
__device__ float g_h   [NTOK * EMB];
__device__ float g_qkv [NTOK * QKV3];
__device__ float g_ctx [NTOK * EMB];
__device__ float g_x1  [NTOK * EMB];
__device__ float g_h2  [NTOK * EMB];
__device__ float g_ff  [NTOK * DFF];
// pre-transposed + tf32-rounded weights
__device__ float g_wqkvT[QKV3 * EMB];
__device__ float g_woT  [EMB * EMB];
__device__ float g_w1T  [DFF * EMB];
__device__ float g_w2T  [EMB * DFF];
__device__ float g_bqkv [QKV3];

// ---------------- helpers ----------------
__device__ __forceinline__ float f2tf(float f) {
    unsigned u;
    asm("cvt.rna.tf32.f32 %0, %1;" : "=r"(u) : "f"(f));
    return __uint_as_float(u);
}

__device__ __forceinline__ void mma8(float* c, const unsigned* a, const unsigned* b) {
    asm volatile(
        "mma.sync.aligned.m16n8k8.row.col.f32.tf32.tf32.f32 "
        "{%0,%1,%2,%3}, {%4,%5,%6,%7}, {%8,%9}, {%0,%1,%2,%3};"
        : "+f"(c[0]), "+f"(c[1]), "+f"(c[2]), "+f"(c[3])
        : "r"(a[0]), "r"(a[1]), "r"(a[2]), "r"(a[3]), "r"(b[0]), "r"(b[1]));
}

__device__ __forceinline__ void ldsm4(unsigned& r0, unsigned& r1, unsigned& r2,
                                      unsigned& r3, uint32_t addr) {
    asm volatile("ldmatrix.sync.aligned.m8n8.x4.shared.b16 {%0,%1,%2,%3}, [%4];"
                 : "=r"(r0), "=r"(r1), "=r"(r2), "=r"(r3) : "r"(addr));
}

#define CP_ASYNC16(dst, src) \
    asm volatile("cp.async.cg.shared.global [%0], [%1], 16;" :: "r"(dst), "l"(src))
#define CP_COMMIT() asm volatile("cp.async.commit_group;")
#define CP_WAIT1()  asm volatile("cp.async.wait_group 1;")
#define CP_WAIT0()  asm volatile("cp.async.wait_group 0;")

__device__ __forceinline__ float block_reduce_sum(float v, float* red) {
    #pragma unroll
    for (int off = 16; off > 0; off >>= 1)
        v += __shfl_xor_sync(0xffffffffu, v, off);
    int w = threadIdx.x >> 5;
    if ((threadIdx.x & 31) == 0) red[w] = v;
    __syncthreads();
    if (threadIdx.x < 32) {
        float t = (threadIdx.x < 8) ? red[threadIdx.x] : 0.0f;
        #pragma unroll
        for (int off = 4; off > 0; off >>= 1)
            t += __shfl_xor_sync(0xffffffffu, t, off);
        if (threadIdx.x == 0) red[0] = t;
    }
    __syncthreads();
    float r = red[0];
    __syncthreads();
    return r;
}

// ---------------- prep: all 6 weight transposes in ONE launch ----------------
__global__ void __launch_bounds__(256) transpose_all(
    const float* __restrict__ Wq, const float* __restrict__ Wk,
    const float* __restrict__ Wv, const float* __restrict__ Wo,
    const float* __restrict__ W1, const float* __restrict__ W2)
{
    const float* src; float* dst; int K, N;
    switch (blockIdx.z) {
        case 0: src = Wq; dst = g_wqkvT;               K = EMB; N = EMB; break;
        case 1: src = Wk; dst = g_wqkvT + EMB * EMB;   K = EMB; N = EMB; break;
        case 2: src = Wv; dst = g_wqkvT + 2*EMB*EMB;   K = EMB; N = EMB; break;
        case 3: src = Wo; dst = g_woT;                 K = EMB; N = EMB; break;
        case 4: src = W1; dst = g_w1T;                 K = EMB; N = DFF; break;
        default:src = W2; dst = g_w2T;                 K = DFF; N = EMB; break;
    }
    const int n0 = blockIdx.x * 32;
    const int k0 = blockIdx.y * 32;
    if (n0 >= N || k0 >= K) return;

    __shared__ float t[32][33];
    const int tx = threadIdx.x & 31;
    const int ty = threadIdx.x >> 5;
    #pragma unroll
    for (int j = 0; j < 4; j++)
        t[ty + j * 8][tx] = src[(size_t)(k0 + ty + j * 8) * N + n0 + tx];
    __syncthreads();
    #pragma unroll
    for (int j = 0; j < 4; j++)
        dst[(size_t)(n0 + ty + j * 8) * K + k0 + tx] = f2tf(t[tx][ty + j * 8]);
}

__global__ void bias_concat(const float* bq, const float* bk, const float* bv,
                            float* out)
{
    int i = blockIdx.x * 256 + threadIdx.x;
    if (i < QKV3) {
        float v = (i < EMB) ? bq[i] : (i < 2 * EMB) ? bk[i - EMB] : bv[i - 2 * EMB];
        out[i] = v;
    }
}

// ---------------- LayerNorm (outputs tf32-rounded) ----------------
__global__ void __launch_bounds__(256) ln_kernel(
    const float* __restrict__ x, const float* __restrict__ gw,
    const float* __restrict__ bw, float* __restrict__ out)
{
    __shared__ float red[32];
    const int row = blockIdx.x;
    const float* xr = x + (size_t)row * EMB;

    float vals[3];
    float lsum = 0.0f;
    #pragma unroll
    for (int i = 0; i < 3; i++) {
        vals[i] = xr[threadIdx.x + i * 256];
        lsum += vals[i];
    }
    float mu = block_reduce_sum(lsum, red) * (1.0f / EMB);

    float ls2 = 0.0f;
    #pragma unroll
    for (int i = 0; i < 3; i++) {
        float d = vals[i] - mu;
        ls2 += d * d;
    }
    float var = block_reduce_sum(ls2, red) * (1.0f / EMB);
    float rs = rsqrtf(var + 1e-5f);

    float* outr = out + (size_t)row * EMB;
    #pragma unroll
    for (int i = 0; i < 3; i++) {
        int c = threadIdx.x + i * 256;
        outr[c] = f2tf((vals[i] - mu) * rs * gw[c] + bw[c]);
    }
}

// ---------------- fused flash attention (tf32 mma.sync; unchanged R4) --------
#define QP 68
#define VP 72
#define PP 132

__global__ void __launch_bounds__(256) flash_kernel(
    const float* __restrict__ qkv, float* __restrict__ ctx)
{
    extern __shared__ float fs[];
    const uint32_t base  = (uint32_t)__cvta_generic_to_shared(fs);
    const uint32_t kBase = base;
    const uint32_t vBase = kBase + 2u * 128 * QP * 4;
    float* Pfs = fs + 2 * 128 * QP + 2 * 128 * VP;

    const int tid  = threadIdx.x;
    const int w    = tid >> 5;
    const int lane = tid & 31;
    const int gi   = lane >> 2;
    const int li   = lane & 3;
    const int q0   = blockIdx.x * 128;
    const int z    = blockIdx.y;
    const int b    = z / HEADS, h = z % HEADS;

    const float* qptr = qkv + (size_t)(b * SEQ + q0) * QKV3 + h * HD;
    const float* kptr = qkv + (size_t)(b * SEQ) * QKV3 + EMB + h * HD;
    const float* vptr = qkv + (size_t)(b * SEQ) * QKV3 + 2 * EMB + h * HD;

    {
        uint32_t dst = vBase + 128u * VP * 4;
        #pragma unroll
        for (int i = 0; i < 8; i++) {
            int idx = tid + i * 256;
            int r = idx >> 4, c = (idx & 15) * 4;
            CP_ASYNC16(dst + (uint32_t)(r * QP + c) * 4, qptr + (size_t)r * QKV3 + c);
        }
    }
    CP_COMMIT();
    CP_WAIT0();
    __syncthreads();

    unsigned qf[8][4];
    {
        uint32_t qb = vBase + 128u * VP * 4;
        int rowA = w * 16 + (lane & 15);
        int kqA  = (lane >> 4) * 4;
        #pragma unroll
        for (int ks = 0; ks < 8; ks++)
            ldsm4(qf[ks][0], qf[ks][1], qf[ks][2], qf[ks][3],
                  qb + (uint32_t)(rowA * QP + ks * 8 + kqA) * 4);
    }
    __syncthreads();

    float m0 = -1e30f, m1 = -1e30f, l0 = 0.0f, l1 = 0.0f;
    float O[8][4];
    #pragma unroll
    for (int nt = 0; nt < 8; nt++)
        #pragma unroll
        for (int t = 0; t < 4; t++) O[nt][t] = 0.0f;

    const int rowB = ((lane >> 4) & 1) * 8 + (lane & 7);
    const int kqB  = ((lane >> 3) & 1) * 4;
    const int prow0 = w * 16 + gi;
    const int prow1 = prow0 + 8;

    {
        #pragma unroll
        for (int i = 0; i < 8; i++) {
            int idx = tid + i * 256;
            int r = idx >> 4, c = (idx & 15) * 4;
            CP_ASYNC16(kBase + (uint32_t)(r * QP + c) * 4, kptr + (size_t)r * QKV3 + c);
            CP_ASYNC16(vBase + (uint32_t)(r * VP + c) * 4, vptr + (size_t)r * QKV3 + c);
        }
        CP_COMMIT();
    }

    for (int t = 0; t < 8; t++) {
        const int st = t & 1;
        if (t < 7) {
            const int ns = st ^ 1;
            const float* kp = kptr + (size_t)(t + 1) * 128 * QKV3;
            const float* vp = vptr + (size_t)(t + 1) * 128 * QKV3;
            uint32_t kd = kBase + (uint32_t)ns * 128 * QP * 4;
            uint32_t vd = vBase + (uint32_t)ns * 128 * VP * 4;
            #pragma unroll
            for (int i = 0; i < 8; i++) {
                int idx = tid + i * 256;
                int r = idx >> 4, c = (idx & 15) * 4;
                CP_ASYNC16(kd + (uint32_t)(r * QP + c) * 4, kp + (size_t)r * QKV3 + c);
                CP_ASYNC16(vd + (uint32_t)(r * VP + c) * 4, vp + (size_t)r * QKV3 + c);
            }
            CP_COMMIT();
            CP_WAIT1();
        } else {
            CP_WAIT0();
        }
        __syncthreads();

        float acc[16][4];
        #pragma unroll
        for (int nt = 0; nt < 16; nt++)
            #pragma unroll
            for (int c = 0; c < 4; c++) acc[nt][c] = 0.0f;

        uint32_t kb = kBase + (uint32_t)st * 128 * QP * 4;
        #pragma unroll
        for (int ks = 0; ks < 8; ks++) {
            unsigned bf[16][2];
            #pragma unroll
            for (int p = 0; p < 8; p++) {
                unsigned r0, r1, r2, r3;
                ldsm4(r0, r1, r2, r3,
                      kb + (uint32_t)((rowB + p * 16) * QP + ks * 8 + kqB) * 4);
                bf[2 * p][0] = r0; bf[2 * p][1] = r1;
                bf[2 * p + 1][0] = r2; bf[2 * p + 1][1] = r3;
            }
            #pragma unroll
            for (int nt = 0; nt < 16; nt++)
                mma8(acc[nt], qf[ks], bf[nt]);
        }

        float mx0 = -1e30f, mx1 = -1e30f;
        #pragma unroll
        for (int nt = 0; nt < 16; nt++) {
            acc[nt][0] *= 0.125f; acc[nt][1] *= 0.125f;
            acc[nt][2] *= 0.125f; acc[nt][3] *= 0.125f;
            mx0 = fmaxf(mx0, fmaxf(acc[nt][0], acc[nt][1]));
            mx1 = fmaxf(mx1, fmaxf(acc[nt][2], acc[nt][3]));
        }
        mx0 = fmaxf(mx0, __shfl_xor_sync(0xffffffffu, mx0, 1));
        mx0 = fmaxf(mx0, __shfl_xor_sync(0xffffffffu, mx0, 2));
        mx1 = fmaxf(mx1, __shfl_xor_sync(0xffffffffu, mx1, 1));
        mx1 = fmaxf(mx1, __shfl_xor_sync(0xffffffffu, mx1, 2));
        float mn0 = fmaxf(m0, mx0), mn1 = fmaxf(m1, mx1);
        float a0 = __expf(m0 - mn0), a1 = __expf(m1 - mn1);
        m0 = mn0; m1 = mn1;

        float s0 = 0.0f, s1 = 0.0f;
        #pragma unroll
        for (int nt = 0; nt < 16; nt++) {
            float p0 = __expf(acc[nt][0] - mn0);
            float p1 = __expf(acc[nt][1] - mn0);
            float p2 = __expf(acc[nt][2] - mn1);
            float p3 = __expf(acc[nt][3] - mn1);
            s0 += p0 + p1; s1 += p2 + p3;
            int col = nt * 8 + 2 * li;
            *(float2*)&Pfs[prow0 * PP + col] = make_float2(f2tf(p0), f2tf(p1));
            *(float2*)&Pfs[prow1 * PP + col] = make_float2(f2tf(p2), f2tf(p3));
        }
        s0 += __shfl_xor_sync(0xffffffffu, s0, 1);
        s0 += __shfl_xor_sync(0xffffffffu, s0, 2);
        s1 += __shfl_xor_sync(0xffffffffu, s1, 1);
        s1 += __shfl_xor_sync(0xffffffffu, s1, 2);
        l0 = l0 * a0 + s0;
        l1 = l1 * a1 + s1;

        #pragma unroll
        for (int nt = 0; nt < 8; nt++) {
            O[nt][0] *= a0; O[nt][1] *= a0;
            O[nt][2] *= a1; O[nt][3] *= a1;
        }
        __syncwarp();

        uint32_t vb = vBase + (uint32_t)st * 128 * VP * 4;
        const unsigned* Pu = (const unsigned*)Pfs;
        #pragma unroll
        for (int kk = 0; kk < 16; kk++) {
            const int k0 = kk * 8;
            unsigned af[4];
            af[0] = Pu[prow0 * PP + k0 + li];
            af[1] = Pu[prow1 * PP + k0 + li];
            af[2] = Pu[prow0 * PP + k0 + li + 4];
            af[3] = Pu[prow1 * PP + k0 + li + 4];
            const unsigned* Vu = (const unsigned*)fs;
            uint32_t vw = (vb - base) >> 2;
            #pragma unroll
            for (int nt = 0; nt < 8; nt++) {
                unsigned bfr[2];
                bfr[0] = Vu[vw + (k0 + li) * VP + nt * 8 + gi];
                bfr[1] = Vu[vw + (k0 + li + 4) * VP + nt * 8 + gi];
                mma8(O[nt], af, bfr);
            }
        }
        __syncthreads();
    }

    float inv0 = 1.0f / l0, inv1 = 1.0f / l1;
    float* out0 = ctx + (size_t)(b * SEQ + q0 + w * 16 + gi) * EMB + h * HD;
    float* out1 = out0 + (size_t)8 * EMB;
    #pragma unroll
    for (int nt = 0; nt < 8; nt++) {
        int col = nt * 8 + 2 * li;
        *(float2*)(out0 + col) = make_float2(f2tf(O[nt][0] * inv0), f2tf(O[nt][1] * inv0));
        *(float2*)(out1 + col) = make_float2(f2tf(O[nt][2] * inv1), f2tf(O[nt][3] * inv1));
    }
}

// ---------------- tf32 GEMM, 2-stage cp.async, ldmatrix, big-M tiles ---------
// BM=256, BN=128, 512 threads (16 warps), WM=64, WN=32.
template<int BM, int BN, int WM, int WN, int THR,
         bool DO_GELU, bool DO_RESID, bool RNA_OUT>
__global__ void __launch_bounds__(THR) mma_gemm(
    const float* __restrict__ A, const float* __restrict__ B,
    const float* __restrict__ bias, const float* __restrict__ R,
    float* __restrict__ C, int M, int N, int K,
    int lda, int ldb, int ldc, float scale)
{
    constexpr int BK = 32, BKP = 36;
    constexpr int MT = WM / 16;
    constexpr int NT = WN / 8;
    constexpr int WARPS_N = BN / WN;
    constexpr int STAGE = (BM + BN) * BKP;

    extern __shared__ unsigned smem[];
    const uint32_t base = (uint32_t)__cvta_generic_to_shared(smem);

    const int tid  = threadIdx.x;
    const int w    = tid >> 5;
    const int lane = tid & 31;
    const int gi   = lane >> 2;
    const int li   = lane & 3;
    const int wn   = w % WARPS_N;
    const int wm   = w / WARPS_N;
    const int bm   = blockIdx.y * BM;
    const int bn   = blockIdx.x * BN;

    const int rowA = wm * WM + (lane & 15);
    const int kqA  = (lane >> 4) * 4;
    const int rowB = wn * WN + ((lane >> 4) & 1) * 8 + (lane & 7);
    const int kqB  = ((lane >> 3) & 1) * 4;

    auto load_tile = [&](int k0, int st) {
        uint32_t sA = base + (uint32_t)st * STAGE * 4;
        uint32_t sB = sA + BM * BKP * 4;
        #pragma unroll
        for (int i = 0; i < (BM * 8) / THR; i++) {
            int idx = tid + i * THR;
            int r = idx >> 3, c = (idx & 7) * 4;
            CP_ASYNC16(sA + (uint32_t)(r * BKP + c) * 4,
                       A + (size_t)(bm + r) * lda + k0 + c);
        }
        #pragma unroll
        for (int i = 0; i < (BN * 8) / THR; i++) {
            int idx = tid + i * THR;
            int r = idx >> 3, c = (idx & 7) * 4;
            CP_ASYNC16(sB + (uint32_t)(r * BKP + c) * 4,
                       B + (size_t)(bn + r) * ldb + k0 + c);
        }
    };

    float acc[MT][NT][4];
    #pragma unroll
    for (int i = 0; i < MT; i++)
        #pragma unroll
        for (int j = 0; j < NT; j++)
            #pragma unroll
            for (int t = 0; t < 4; t++) acc[i][j][t] = 0.0f;

    const int iters = K / BK;
    load_tile(0, 0);
    CP_COMMIT();

    for (int it = 0; it < iters; ++it) {
        const int st = it & 1;
        if (it + 1 < iters) load_tile((it + 1) * BK, st ^ 1);
        CP_COMMIT();
        CP_WAIT1();
        __syncthreads();

        uint32_t sA = base + (uint32_t)st * STAGE * 4;
        uint32_t sB = sA + BM * BKP * 4;

        #pragma unroll
        for (int ks = 0; ks < BK / 8; ks++) {
            const int kb = ks * 8;
            unsigned af[MT][4];
            #pragma unroll
            for (int mt = 0; mt < MT; mt++) {
                uint32_t ad = sA + (uint32_t)((rowA + mt * 16) * BKP + kb + kqA) * 4;
                ldsm4(af[mt][0], af[mt][1], af[mt][2], af[mt][3], ad);
            }
            unsigned bf[NT][2];
            #pragma unroll
            for (int p = 0; p < NT / 2; p++) {
                uint32_t ad = sB + (uint32_t)((rowB + p * 16) * BKP + kb + kqB) * 4;
                unsigned r0, r1, r2, r3;
                ldsm4(r0, r1, r2, r3, ad);
                bf[2 * p][0] = r0; bf[2 * p][1] = r1;
                bf[2 * p + 1][0] = r2; bf[2 * p + 1][1] = r3;
            }
            #pragma unroll
            for (int mt = 0; mt < MT; mt++)
                #pragma unroll
                for (int nt = 0; nt < NT; nt++)
                    mma8(acc[mt][nt], af[mt], bf[nt]);
        }
        __syncthreads();
    }

    #pragma unroll
    for (int mt = 0; mt < MT; mt++) {
        #pragma unroll
        for (int nt = 0; nt < NT; nt++) {
            int row = bm + wm * WM + mt * 16 + gi;
            int col = bn + wn * WN + nt * 8 + 2 * li;
            float bi0 = 0.0f, bi1 = 0.0f;
            if (bias) { bi0 = bias[col]; bi1 = bias[col + 1]; }
            #pragma unroll
            for (int half = 0; half < 2; half++) {
                int rr = row + half * 8;
                float v0 = acc[mt][nt][half * 2 + 0] * scale + bi0;
                float v1 = acc[mt][nt][half * 2 + 1] * scale + bi1;
                if (DO_GELU) {
                    v0 = 0.5f * v0 * (1.0f + erff(v0 * 0.70710678118654752f));
                    v1 = 0.5f * v1 * (1.0f + erff(v1 * 0.70710678118654752f));
                }
                if (DO_RESID) {
                    float2 r2 = *(const float2*)(R + (size_t)rr * ldc + col);
                    v0 += r2.x; v1 += r2.y;
                }
                if (RNA_OUT) { v0 = f2tf(v0); v1 = f2tf(v1); }
                *(float2*)(C + (size_t)rr * ldc + col) = make_float2(v0, v1);
            }
        }
    }
}

// ---------------- launch ----------------
extern "C" void kernel_launch(void* const* d_in, const int* in_sizes, int n_in,
                              void* d_out, int out_size)
{
    const float* x     = (const float*)d_in[0];
    const float* ln1_g = (const float*)d_in[1];
    const float* ln1_b = (const float*)d_in[2];
    const float* Wq    = (const float*)d_in[3];
    const float* bq    = (const float*)d_in[4];
    const float* Wk    = (const float*)d_in[5];
    const float* bk    = (const float*)d_in[6];
    const float* Wv    = (const float*)d_in[7];
    const float* bv    = (const float*)d_in[8];
    const float* Wo    = (const float*)d_in[9];
    const float* bo    = (const float*)d_in[10];
    const float* ln2_g = (const float*)d_in[11];
    const float* ln2_b = (const float*)d_in[12];
    const float* W1    = (const float*)d_in[13];
    const float* b1    = (const float*)d_in[14];
    const float* W2    = (const float*)d_in[15];
    const float* b2    = (const float*)d_in[16];
    float* out = (float*)d_out;

    float *h, *qkv, *ctx, *x1, *h2, *ff;
    float *wqkvT, *woT, *w1T, *w2T, *bqkv;
    cudaGetSymbolAddress((void**)&h,     g_h);
    cudaGetSymbolAddress((void**)&qkv,   g_qkv);
    cudaGetSymbolAddress((void**)&ctx,   g_ctx);
    cudaGetSymbolAddress((void**)&x1,    g_x1);
    cudaGetSymbolAddress((void**)&h2,    g_h2);
    cudaGetSymbolAddress((void**)&ff,    g_ff);
    cudaGetSymbolAddress((void**)&wqkvT, g_wqkvT);
    cudaGetSymbolAddress((void**)&woT,   g_woT);
    cudaGetSymbolAddress((void**)&w1T,   g_w1T);
    cudaGetSymbolAddress((void**)&w2T,   g_w2T);
    cudaGetSymbolAddress((void**)&bqkv,  g_bqkv);

    const int SM_BIG   = 2 * (256 + 128) * 36 * 4;                        // 110592
    const int SM_FLASH = (2 * 128 * QP + 2 * 128 * VP + 8 * 16 * PP) * 4; // 210944

    cudaFuncSetAttribute((const void*)mma_gemm<256,128,64,32,512,false,false,true>,
                         cudaFuncAttributeMaxDynamicSharedMemorySize, SM_BIG);
    cudaFuncSetAttribute((const void*)mma_gemm<256,128,64,32,512,false,true,false>,
                         cudaFuncAttributeMaxDynamicSharedMemorySize, SM_BIG);
    cudaFuncSetAttribute((const void*)mma_gemm<256,128,64,32,512,true,false,true>,
                         cudaFuncAttributeMaxDynamicSharedMemorySize, SM_BIG);
    cudaFuncSetAttribute((const void*)flash_kernel,
                         cudaFuncAttributeMaxDynamicSharedMemorySize, SM_FLASH);

    // 0. bias concat
    bias_concat<<<9, 256>>>(bq, bk, bv, bqkv);
    // 1. all weight transposes (single launch)
    transpose_all<<<dim3(96, 96, 6), 256>>>(Wq, Wk, Wv, Wo, W1, W2);
    // 2. LN1
    ln_kernel<<<NTOK, 256>>>(x, ln1_g, ln1_b, h);
    // 3. fused QKV (outputs tf32-rounded)
    mma_gemm<256,128,64,32,512,false,false,true><<<dim3(QKV3/128, NTOK/256), 512, SM_BIG>>>(
        h, wqkvT, bqkv, nullptr, qkv, NTOK, QKV3, EMB, EMB, EMB, QKV3, 1.0f);
    // 4. fused flash attention -> ctx (tf32-rounded)
    flash_kernel<<<dim3(SEQ/128, BATCH*HEADS), 256, SM_FLASH>>>(qkv, ctx);
    // 5. x1 = ctx @ Wo + bo + x          <-- ncu capture target
    mma_gemm<256,128,64,32,512,false,true,false><<<dim3(EMB/128, NTOK/256), 512, SM_BIG>>>(
        ctx, woT, bo, x, x1, NTOK, EMB, EMB, EMB, EMB, EMB, 1.0f);
    // 6. LN2
    ln_kernel<<<NTOK, 256>>>(x1, ln2_g, ln2_b, h2);
    // 7. ff = rna(gelu(h2 @ W1 + b1))
    mma_gemm<256,128,64,32,512,true,false,true><<<dim3(DFF/128, NTOK/256), 512, SM_BIG>>>(
        h2, w1T, b1, nullptr, ff, NTOK, DFF, EMB, EMB, EMB, DFF, 1.0f);
    // 8. out = ff @ W2 + b2 + x1
    mma_gemm<256,128,64,32,512,false,true,false><<<dim3(EMB/128, NTOK/256), 512, SM_BIG>>>(
        ff, w2T, b2, x1, out, NTOK, EMB, DFF, DFF, DFF, EMB, 1.0f);
}